// round 8
// baseline (speedup 1.0000x reference)
#include <cuda_runtime.h>
#include <cstdint>
#include <math.h>

#define D_DIM   1024
#define T_DIM   50
#define STRIDEQ 10
#define NUM_POS 16
#define MAX_B   4096
#define MAX_KP  13108   /* ceil(131072/10) */
#define CHUNK   512     /* eval/early-exit granularity (== blockDim) */
#define NWMAX   416     /* ceil(13108/32)=410, padded */

// ---- device scratch (static; no allocations allowed) ----
__device__ ulonglong2 g_q[MAX_KP];
__device__ ulonglong2 g_a[MAX_B];
__device__ float      g_per[MAX_B];
__device__ unsigned   g_counter;

// ------------------------------------------------------------------
// Kernel 1: pack labels (strided queue rows + anchors). Warp per row.
// ------------------------------------------------------------------
__global__ void prep_labels(const int* __restrict__ xlab,
                            const int* __restrict__ qlab,
                            int B, int Kp) {
    if (blockIdx.x == 0 && threadIdx.x == 0) g_counter = 0;
    int warp = (blockIdx.x * blockDim.x + threadIdx.x) >> 5;
    int lane = threadIdx.x & 31;
    if (warp >= Kp + B) return;

    const int* lp = (warp < Kp)
        ? qlab + (long long)warp * STRIDEQ * (T_DIM * 2)
        : xlab + (long long)(warp - Kp) * (T_DIM * 2);

    int2 va = ((const int2*)lp)[lane];
    int l0b = 0, l1b = 0;
    if (32 + lane < T_DIM) {
        int2 vb = ((const int2*)lp)[32 + lane];
        l0b = vb.x; l1b = vb.y;
    }
    unsigned b0lo = __ballot_sync(0xffffffffu, va.x != 0);
    unsigned b1lo = __ballot_sync(0xffffffffu, va.y != 0);
    unsigned b0hi = __ballot_sync(0xffffffffu, l0b != 0);
    unsigned b1hi = __ballot_sync(0xffffffffu, l1b != 0);
    if (lane == 0) {
        ulonglong2 v;
        v.x = (unsigned long long)b0lo | ((unsigned long long)b0hi << 32);
        v.y = (unsigned long long)b1lo | ((unsigned long long)b1hi << 32);
        if (warp < Kp) g_q[warp]      = v;
        else           g_a[warp - Kp] = v;
    }
}

// ------------------------------------------------------------------
// Predicate (exact fp32, validated R1-R6).
// ------------------------------------------------------------------
__device__ __forceinline__ bool pair_pred(
    unsigned long long a0, unsigned long long a1,
    unsigned long long da, unsigned long long xa,
    unsigned long long q0, unsigned long long q1,
    float c, float d2) {
    unsigned long long dq = q0 & q1;
    unsigned long long xk = q0 ^ q1;
    unsigned long long m1  = (xa & xk) & ~(a0 ^ q0);
    unsigned long long mc  = (da & xk) | (xa & dq);
    unsigned long long mdd = da & dq;
    float s = (float)__popcll(m1)
            + (float)__popcll(mc)  * c
            + (float)__popcll(mdd) * d2;
    return s >= 25.0f;
}

// ------------------------------------------------------------------
// Kernel 2 (fused): per-anchor select (512-thread parallel, chunked
// early exit) + 16 gathered dots + loss + last-block mean.
// ------------------------------------------------------------------
__global__ void __launch_bounds__(512)
fused_kernel(const float* __restrict__ xq, const float* __restrict__ qf,
             float* __restrict__ out, int B, int Kp) {
    // 16B/8B-aligned first, then 4B arrays: explicit alignment safety.
    __shared__ float4   s_anchor4[D_DIM / 4];   // 16B aligned
    __shared__ double   s_red[512];             // 8B aligned
    __shared__ unsigned s_words[NWMAX];
    __shared__ float    s_ssq[256];
    __shared__ float    s_loss[NUM_POS];
    __shared__ int      s_sel[NUM_POS];
    __shared__ int      s_total;
    __shared__ int      s_cnt;
    __shared__ int      s_last;

    const float* s_anchor = (const float*)s_anchor4;

    int b    = blockIdx.x;
    int tid  = threadIdx.x;
    int w    = tid >> 5;
    int lane = tid & 31;

    // ---- stage anchor row (threads 256..511; load overlaps eval) ----
    if (tid >= 256) {
        int i = tid - 256;
        float4 v = ((const float4*)(xq + (long long)b * D_DIM))[i];
        s_anchor4[i] = v;
        s_ssq[i] = v.x * v.x + v.y * v.y + v.z * v.z + v.w * v.w;
    }
    if (tid == 0) s_total = 0;

    // ---- anchor labels (broadcast) ----
    ulonglong2 av = g_a[b];
    unsigned long long a0 = av.x, a1 = av.y;
    unsigned long long da = a0 & a1, xa = a0 ^ a1;
    float c  = 1.0f / (sqrtf(2.0f) + 1e-8f);
    float cc = c * c;
    float d2 = cc + cc;
    __syncthreads();

    // ---- chunked predicate eval, all 512 threads, early exit ----
    int scan_end = 0;
#pragma unroll 1
    for (int base = 0; base < Kp; base += CHUNK) {
        int k = base + tid;
        bool pred = false;
        if (k < Kp) {
            ulonglong2 qv = g_q[k];
            pred = pair_pred(a0, a1, da, xa, qv.x, qv.y, c, d2);
        }
        unsigned m = __ballot_sync(0xffffffffu, pred);
        if (lane == 0) s_words[(base >> 5) + w] = m;
        __syncthreads();
        if (w == 0) {
            int cw = (lane < 16) ? __popc(s_words[(base >> 5) + lane]) : 0;
#pragma unroll
            for (int o = 16; o; o >>= 1) cw += __shfl_xor_sync(0xffffffffu, cw, o);
            if (lane == 0) s_total += cw;
        }
        __syncthreads();
        scan_end = (base + CHUNK < Kp) ? base + CHUNK : Kp;
        if (s_total >= NUM_POS) break;
    }

    // ---- ordered extraction of first <=16 hits (warp 0) ----
    if (w == 0) {
        int nwords = (scan_end + 31) >> 5;
        int run = 0;
        for (int g = 0; g * 32 < nwords && run < NUM_POS; g++) {
            int wi = g * 32 + lane;
            unsigned word = (wi < nwords) ? s_words[wi] : 0u;
            int my = __popc(word);
            int pre = my;
#pragma unroll
            for (int o = 1; o < 32; o <<= 1) {
                int v = __shfl_up_sync(0xffffffffu, pre, o);
                if (lane >= o) pre += v;
            }
            int gtot = __shfl_sync(0xffffffffu, pre, 31);
            int rank = run + pre - my;
            while (word && rank < NUM_POS) {
                int bit = __ffs(word) - 1;
                word &= word - 1;
                s_sel[rank++] = wi * 32 + bit;
            }
            run += gtot;
        }
        if (lane == 0) {
            int t = s_total;
            s_cnt = (t < NUM_POS) ? t : NUM_POS;
        }
    }
    __syncthreads();

    // ---- 16 gathered dots with fused norms (validated path) ----
    int cnt = s_cnt;
    float loss = 0.f;
    if (w < cnt) {
        int kp = s_sel[w];
        const float4* pk = (const float4*)(qf + (long long)kp * STRIDEQ * D_DIM);
        const float4* pa = (const float4*)s_anchor4;
        float dot = 0.f, kss = 0.f;
#pragma unroll
        for (int i = 0; i < D_DIM / 4 / 32; i++) {
            float4 a  = pa[lane + i * 32];
            float4 kk = pk[lane + i * 32];
            dot += a.x * kk.x + a.y * kk.y + a.z * kk.z + a.w * kk.w;
            kss += kk.x * kk.x + kk.y * kk.y + kk.z * kk.z + kk.w * kk.w;
        }
#pragma unroll
        for (int o = 16; o; o >>= 1) {
            dot += __shfl_xor_sync(0xffffffffu, dot, o);
            kss += __shfl_xor_sync(0xffffffffu, kss, o);
        }
        float qss = s_ssq[lane] + s_ssq[lane + 32] + s_ssq[lane + 64]
                  + s_ssq[lane + 96] + s_ssq[lane + 128] + s_ssq[lane + 160]
                  + s_ssq[lane + 192] + s_ssq[lane + 224];
#pragma unroll
        for (int o = 16; o; o >>= 1) qss += __shfl_xor_sync(0xffffffffu, qss, o);

        float inv_q = 1.0f / (sqrtf(qss) + 1e-8f);
        float inv_k = 1.0f / (sqrtf(kss) + 1e-8f);
        float s = dot * inv_q * inv_k * 2.0f;     // / TEMPERATURE(0.5)
        float z = -s;                              // -log_sigmoid(s)
        loss = fmaxf(z, 0.f) + log1pf(expf(-fabsf(z)));
    }
    if (lane == 0 && w < NUM_POS) s_loss[w] = loss;
    __syncthreads();

    if (tid == 0) {
        float sum = 0.f;
#pragma unroll
        for (int i = 0; i < NUM_POS; i++) sum += (i < cnt) ? s_loss[i] : 0.f;
        g_per[b] = (cnt > 0) ? (sum / (float)cnt) : 0.f;
        __threadfence();
        unsigned t = atomicAdd(&g_counter, 1u);
        s_last = (t == (unsigned)(gridDim.x - 1)) ? 1 : 0;
    }
    __syncthreads();

    // ---- last block: deterministic double-precision mean ----
    if (s_last) {
        double acc = 0.0;
        for (int i = tid; i < B; i += 512) acc += (double)g_per[i];
        s_red[tid] = acc;
        __syncthreads();
        for (int s = 256; s; s >>= 1) {
            if (tid < s) s_red[tid] += s_red[tid + s];
            __syncthreads();
        }
        if (tid == 0) out[0] = (float)(s_red[0] / (double)B);
    }
}

extern "C" void kernel_launch(void* const* d_in, const int* in_sizes, int n_in,
                              void* d_out, int out_size) {
    const float* xq   = (const float*)d_in[0];
    const int*   xlab = (const int*)  d_in[1];
    const float* qf   = (const float*)d_in[2];
    const int*   qlab = (const int*)  d_in[3];

    int B  = in_sizes[0] / D_DIM;                 // 4096
    int K  = in_sizes[2] / D_DIM;                 // 131072
    int Kp = (K + STRIDEQ - 1) / STRIDEQ;         // 13108

    int warps  = Kp + B;
    int blocks = (warps * 32 + 255) / 256;
    prep_labels <<<blocks, 256>>>(xlab, qlab, B, Kp);
    fused_kernel<<<B, 512>>>(xq, qf, (float*)d_out, B, Kp);
}